// round 16
// baseline (speedup 1.0000x reference)
#include <cuda_runtime.h>
#include <cstdint>

// Haar IDWT2: out[2i,2j]=(LL+LH+HL+HH)/2, out[2i,2j+1]=(LL+LH-HL-HH)/2,
//             out[2i+1,2j]=(LL-LH+HL-HH)/2, out[2i+1,2j+1]=(LL-LH-HL+HH)/2
// Shapes: inputs [B,C,H2,W2] = [16,64,128,128] fp32; output [B,C,256,256] fp32.
//
// FINAL (converged; best-of-5 runs 80.35us bench, 73.6us ncu, 6.57 TB/s):
// 2 coeffs/thread, block=512, 16 regs, one-shot dense grid.
//  - Loads: float2 x 4 subbands; warp = 256B contiguous per subband.
//  - Stores: one float4 per output row; warp = 512B contiguous per row.
//    Minimal L1 wavefronts on both sides.
//  - Traffic = exactly 512 MiB (read 256 + write 256), zero amplification.
// Falsified levers: 2x MLP (neutral), __ldcs/__stcs (-1.5%), __stwt
// (neutral), block 256 (-2%), persistent grid-stride (-7%: HW dispatcher's
// dense rolling wavefront beats resident blocks for DRAM page locality).
// Binding constraint: HBM read<->write turnaround on a 50/50 single-pass
// stream (~82% bus-active ceiling). Not kernel-addressable.

static constexpr int Bdim = 16;
static constexpr int Cdim = 64;
static constexpr int H2   = 128;
static constexpr int W2   = 128;
static constexpr int W2V2 = W2 / 2;              // float2 groups per input row = 64
static constexpr long long NCOEF = (long long)Bdim * Cdim * H2 * W2;   // 16,777,216
static constexpr int NTHREADS_TOTAL = (int)(NCOEF / 2);                // 8,388,608

__global__ __launch_bounds__(512)
void idwt_haar_kernel(const float2* __restrict__ LL2,
                      const float2* __restrict__ LH2,
                      const float2* __restrict__ HL2,
                      const float2* __restrict__ HH2,
                      float* __restrict__ out)
{
    int tid = blockIdx.x * blockDim.x + threadIdx.x;
    int col2 = tid & (W2V2 - 1);         // 0..63
    int row  = tid >> 6;                 // global coefficient row index

    long long in_off = (long long)row * W2V2 + col2;
    float2 ll = __ldg(&LL2[in_off]);
    float2 lh = __ldg(&LH2[in_off]);
    float2 hl = __ldg(&HL2[in_off]);
    float2 hh = __ldg(&HH2[in_off]);

    // butterflies (x0.5)
    float s0 = ll.x + lh.x, t0 = ll.x - lh.x;
    float u0 = hl.x + hh.x, v0 = hl.x - hh.x;
    float a0 = (s0 + u0) * 0.5f;
    float b0 = (s0 - u0) * 0.5f;
    float c0 = (t0 + v0) * 0.5f;
    float d0 = (t0 - v0) * 0.5f;

    float s1 = ll.y + lh.y, t1 = ll.y - lh.y;
    float u1 = hl.y + hh.y, v1 = hl.y - hh.y;
    float a1 = (s1 + u1) * 0.5f;
    float b1 = (s1 - u1) * 0.5f;
    float c1 = (t1 + v1) * 0.5f;
    float d1 = (t1 - v1) * 0.5f;

    // output addressing
    int bc = row >> 7;                   // row / H2
    int i  = row & (H2 - 1);
    const int OW = 2 * W2;               // 256
    long long obase = ((long long)bc * (2 * H2) + 2 * i) * OW + (long long)col2 * 4;

    *reinterpret_cast<float4*>(out + obase)      = make_float4(a0, b0, a1, b1);
    *reinterpret_cast<float4*>(out + obase + OW) = make_float4(c0, d0, c1, d1);
}

extern "C" void kernel_launch(void* const* d_in, const int* in_sizes, int n_in,
                              void* d_out, int out_size)
{
    const float2* LL = (const float2*)d_in[0];
    const float2* LH = (const float2*)d_in[1];
    const float2* HL = (const float2*)d_in[2];
    const float2* HH = (const float2*)d_in[3];
    float* out = (float*)d_out;

    const int threads = 512;
    const int blocks = NTHREADS_TOTAL / threads;   // 16384
    idwt_haar_kernel<<<blocks, threads>>>(LL, LH, HL, HH, out);
}

// round 17
// speedup vs baseline: 1.0008x; 1.0008x over previous
#include <cuda_runtime.h>
#include <cstdint>

// Haar IDWT2: out[2i,2j]=(LL+LH+HL+HH)/2, out[2i,2j+1]=(LL+LH-HL-HH)/2,
//             out[2i+1,2j]=(LL-LH+HL-HH)/2, out[2i+1,2j+1]=(LL-LH-HL+HH)/2
// Shapes: inputs [B,C,H2,W2] = [16,64,128,128] fp32; output [B,C,256,256] fp32.
//
// FINAL (converged; 6 runs: bench 80.35-81.31us, ncu 73.6-75.2us, ~6.5TB/s):
// 2 coeffs/thread, block=512, 16 regs, one-shot dense grid.
//  - Loads: float2 x 4 subbands; warp = 256B contiguous per subband.
//  - Stores: one float4 per output row; warp = 512B contiguous per row.
//    Minimal L1 wavefronts on both sides.
//  - Traffic = exactly 512 MiB (read 256 + write 256), zero amplification:
//    measured bytes == logical minimum.
// Falsified levers: 2x MLP (neutral), __ldcs/__stcs (-1.5%), __stwt
// (neutral), block 256 (-2%), persistent grid-stride (-7%: HW dispatcher's
// dense rolling wavefront beats resident blocks for DRAM page locality).
// Binding constraint: HBM read<->write turnaround on a 50/50 single-pass
// stream (~82% bus-active ceiling). Not kernel-addressable.

static constexpr int Bdim = 16;
static constexpr int Cdim = 64;
static constexpr int H2   = 128;
static constexpr int W2   = 128;
static constexpr int W2V2 = W2 / 2;              // float2 groups per input row = 64
static constexpr long long NCOEF = (long long)Bdim * Cdim * H2 * W2;   // 16,777,216
static constexpr int NTHREADS_TOTAL = (int)(NCOEF / 2);                // 8,388,608

__global__ __launch_bounds__(512)
void idwt_haar_kernel(const float2* __restrict__ LL2,
                      const float2* __restrict__ LH2,
                      const float2* __restrict__ HL2,
                      const float2* __restrict__ HH2,
                      float* __restrict__ out)
{
    int tid = blockIdx.x * blockDim.x + threadIdx.x;
    int col2 = tid & (W2V2 - 1);         // 0..63
    int row  = tid >> 6;                 // global coefficient row index

    long long in_off = (long long)row * W2V2 + col2;
    float2 ll = __ldg(&LL2[in_off]);
    float2 lh = __ldg(&LH2[in_off]);
    float2 hl = __ldg(&HL2[in_off]);
    float2 hh = __ldg(&HH2[in_off]);

    // butterflies (x0.5)
    float s0 = ll.x + lh.x, t0 = ll.x - lh.x;
    float u0 = hl.x + hh.x, v0 = hl.x - hh.x;
    float a0 = (s0 + u0) * 0.5f;
    float b0 = (s0 - u0) * 0.5f;
    float c0 = (t0 + v0) * 0.5f;
    float d0 = (t0 - v0) * 0.5f;

    float s1 = ll.y + lh.y, t1 = ll.y - lh.y;
    float u1 = hl.y + hh.y, v1 = hl.y - hh.y;
    float a1 = (s1 + u1) * 0.5f;
    float b1 = (s1 - u1) * 0.5f;
    float c1 = (t1 + v1) * 0.5f;
    float d1 = (t1 - v1) * 0.5f;

    // output addressing
    int bc = row >> 7;                   // row / H2
    int i  = row & (H2 - 1);
    const int OW = 2 * W2;               // 256
    long long obase = ((long long)bc * (2 * H2) + 2 * i) * OW + (long long)col2 * 4;

    *reinterpret_cast<float4*>(out + obase)      = make_float4(a0, b0, a1, b1);
    *reinterpret_cast<float4*>(out + obase + OW) = make_float4(c0, d0, c1, d1);
}

extern "C" void kernel_launch(void* const* d_in, const int* in_sizes, int n_in,
                              void* d_out, int out_size)
{
    const float2* LL = (const float2*)d_in[0];
    const float2* LH = (const float2*)d_in[1];
    const float2* HL = (const float2*)d_in[2];
    const float2* HH = (const float2*)d_in[3];
    float* out = (float*)d_out;

    const int threads = 512;
    const int blocks = NTHREADS_TOTAL / threads;   // 16384
    idwt_haar_kernel<<<blocks, threads>>>(LL, LH, HL, HH, out);
}